// round 12
// baseline (speedup 1.0000x reference)
#include <cuda_runtime.h>
#include <cuda_fp16.h>
#include <math.h>
#include <mma.h>

using namespace nvcuda;

#define N_NODES   100000
#define N_EDGES   1600000
#define NUM_GRAPHS 64
#define IN_CH     128
#define HID       64
#define NUM_CLASSES 10

#define SCAN_BS   256
#define SCAN_IT   4
#define SCAN_CHUNK (SCAN_BS * SCAN_IT)
#define SCAN_NBLK ((N_NODES + SCAN_CHUNK - 1) / SCAN_CHUNK)  // 98
#define LB_FLAG   (1 << 30)

// ---------------- scratch ----------------
__device__ int   g_cnt[N_NODES];            // zero-init; scatter restores to zero
__device__ float g_dinv[N_NODES];
__device__ int   g_rowptr[N_NODES + 1];
__device__ int   g_ecol[N_EDGES];           // CSR col = src node (norm factored out!)
__device__ int   g_look[SCAN_NBLK];
__device__ __align__(128) float g_t[(size_t)N_NODES * HID];   // GEMM outputs (dinv-scaled)
__device__ __align__(128) float g_h[(size_t)N_NODES * HID];   // prop outputs
__device__ __align__(128) float g_t10[(size_t)N_NODES * NUM_CLASSES];
__device__ float g_pool[NUM_GRAPHS * NUM_CLASSES];  // zero-init; final restores
__device__ float g_pcnt[NUM_GRAPHS];

// ---------------- degree count (+ clears lookback words) ----------------
__global__ void count_kernel(const int* __restrict__ ei) {
    int e = blockIdx.x * blockDim.x + threadIdx.x;
    if (e < SCAN_NBLK) g_look[e] = 0;
    if (e < N_EDGES) atomicAdd(&g_cnt[ei[N_EDGES + e]], 1);
}

// ---------------- fused dinv + exclusive scan (decoupled lookback) ----------------
__global__ void build_rowptr() {
    int b = blockIdx.x, t = threadIdx.x;
    int lane = t & 31, warp = t >> 5;
    int i0 = b * SCAN_CHUNK + t * SCAN_IT;
    int v[SCAN_IT]; int s = 0;
    #pragma unroll
    for (int i = 0; i < SCAN_IT; i++) {
        int idx = i0 + i;
        int c = 0;
        if (idx < N_NODES) {
            c = g_cnt[idx];
            g_dinv[idx] = rsqrtf((float)(c + 1));
        }
        s += c; v[i] = s;
    }
    int x = s;
    #pragma unroll
    for (int off = 1; off < 32; off <<= 1) {
        int y = __shfl_up_sync(0xffffffffu, x, off);
        if (lane >= off) x += y;
    }
    __shared__ int ws[8];
    __shared__ int s_base;
    if (lane == 31) ws[warp] = x;
    if (t == 0) s_base = 0;

    int contrib = 0;
    if (t < b) {
        volatile int* lk = (volatile int*)&g_look[t];
        int val = *lk;
        while (val < LB_FLAG) { __nanosleep(64); val = *lk; }
        contrib = val - LB_FLAG;
    }
    __syncthreads();
    if (warp == 0 && lane < 8) {
        int w = ws[lane];
        int iw = w;
        #pragma unroll
        for (int off = 1; off < 8; off <<= 1) {
            int y = __shfl_up_sync(0xffu, iw, off);
            if (lane >= off) iw += y;
        }
        ws[lane] = iw - w;
        if (lane == 7) atomicExch(&g_look[b], iw | LB_FLAG);
    }
    #pragma unroll
    for (int off = 16; off; off >>= 1) contrib += __shfl_down_sync(0xffffffffu, contrib, off);
    if (lane == 0 && contrib) atomicAdd(&s_base, contrib);
    __syncthreads();

    int excl = s_base + ws[warp] + (x - s);
    #pragma unroll
    for (int i = 0; i < SCAN_IT; i++) {
        int idx = i0 + i;
        if (idx < N_NODES) g_rowptr[idx + 1] = excl + v[i];
    }
    if (b == 0 && t == 0) g_rowptr[0] = 0;
}

// ---------------- CSR scatter (src index only — no norms) ----------------
__global__ void scatter_kernel(const int* __restrict__ ei) {
    int e = blockIdx.x * blockDim.x + threadIdx.x;
    if (e < N_EDGES) {
        int s = ei[e];
        int d = ei[N_EDGES + e];
        int pos = g_rowptr[d] + atomicSub(&g_cnt[d], 1) - 1;
        g_ecol[pos] = s;
    }
}

// ---------------- single-stage HMMA GEMM: [n x K] @ [K x 64] -> fp32 [n x 64], rows x dinv ----------------
template <int K>
__global__ void gemm64_hmma(const float* __restrict__ A, const float* __restrict__ W,
                            float* __restrict__ C, int n) {
    constexpr int AST = K + 8;
    extern __shared__ char smraw[];
    __half (*Ash)[AST] = reinterpret_cast<__half(*)[AST]>(smraw);
    __half (*Wsh)[72]  = reinterpret_cast<__half(*)[72]>(smraw + 128 * AST * 2);
    float* Cs = reinterpret_cast<float*>(smraw);
    int tid = threadIdx.x, wid = tid >> 5, lane = tid & 31;
    int wm = wid >> 1, wn = wid & 1;
    int n0 = blockIdx.x * 128;

    // stage W: K*64 fp32 -> half smem
    #pragma unroll
    for (int i = tid; i < K * 16; i += 256) {
        float4 w = reinterpret_cast<const float4*>(W)[i];
        int k = (i * 4) >> 6, c = (i * 4) & 63;
        __half2* dst = reinterpret_cast<__half2*>(&Wsh[k][c]);
        dst[0] = __floats2half2_rn(w.x, w.y);
        dst[1] = __floats2half2_rn(w.z, w.w);
    }

    // stage A tile (fp32 -> half)
    #pragma unroll
    for (int i = 0; i < (128 * K / 4) / 256; i++) {
        int f4 = tid + i * 256;
        int r  = f4 / (K / 4);
        int c4 = (f4 % (K / 4)) * 4;
        int gr = n0 + r;
        float4 v = (gr < n)
            ? *reinterpret_cast<const float4*>(A + (size_t)gr * K + c4)
            : make_float4(0.f, 0.f, 0.f, 0.f);
        __half2* dst = reinterpret_cast<__half2*>(&Ash[r][c4]);
        dst[0] = __floats2half2_rn(v.x, v.y);
        dst[1] = __floats2half2_rn(v.z, v.w);
    }
    __syncthreads();

    wmma::fragment<wmma::accumulator, 16, 16, 16, float> cf[2][2];
    #pragma unroll
    for (int mm = 0; mm < 2; mm++)
        #pragma unroll
        for (int nn = 0; nn < 2; nn++)
            wmma::fill_fragment(cf[mm][nn], 0.0f);

    #pragma unroll
    for (int ks = 0; ks < K / 16; ks++) {
        wmma::fragment<wmma::matrix_a, 16, 16, 16, __half, wmma::row_major> af[2];
        wmma::fragment<wmma::matrix_b, 16, 16, 16, __half, wmma::row_major> bf[2];
        #pragma unroll
        for (int mm = 0; mm < 2; mm++)
            wmma::load_matrix_sync(af[mm], &Ash[wm * 32 + mm * 16][ks * 16], AST);
        #pragma unroll
        for (int nn = 0; nn < 2; nn++)
            wmma::load_matrix_sync(bf[nn], &Wsh[ks * 16][wn * 32 + nn * 16], 72);
        #pragma unroll
        for (int mm = 0; mm < 2; mm++)
            #pragma unroll
            for (int nn = 0; nn < 2; nn++)
                wmma::mma_sync(cf[mm][nn], af[mm], bf[nn], cf[mm][nn]);
    }
    __syncthreads();

    float* Cw = Cs + wid * (32 * 36);
    #pragma unroll
    for (int mm = 0; mm < 2; mm++)
        #pragma unroll
        for (int nn = 0; nn < 2; nn++)
            wmma::store_matrix_sync(Cw + mm * 16 * 36 + nn * 16, cf[mm][nn], 36, wmma::mem_row_major);
    __syncwarp();

    int gr = n0 + wm * 32 + lane;
    if (gr < n) {
        float dsc = g_dinv[gr];
        float4* dst = reinterpret_cast<float4*>(C + (size_t)gr * 64 + wn * 32);
        const float* src = Cw + lane * 36;
        #pragma unroll
        for (int cc = 0; cc < 8; cc++)
            dst[cc] = make_float4(src[cc * 4] * dsc, src[cc * 4 + 1] * dsc,
                                  src[cc * 4 + 2] * dsc, src[cc * 4 + 3] * dsc);
    }
}

// ---------------- GEMM: fp32 [n x 64] @ [64 x 10] -> fp32 [n x 10], rows x dinv ----------------
__global__ void gemm_out10(const float* __restrict__ A, const float* __restrict__ W,
                           float* __restrict__ C, int n) {
    __shared__ float Ws[64][10];
    __shared__ float As[16][257];
    int tid = threadIdx.x;
    for (int i = tid; i < 640; i += 256) Ws[i / 10][i % 10] = W[i];
    int n0 = blockIdx.x * 256;
    float acc[10];
    #pragma unroll
    for (int c = 0; c < 10; c++) acc[c] = 0.f;

    for (int k0 = 0; k0 < 64; k0 += 16) {
        #pragma unroll
        for (int i = 0; i < 4; i++) {
            int flat4 = tid + i * 256;
            int node = flat4 >> 2;
            int kp = (flat4 & 3) * 4;
            int gn = n0 + node;
            float4 v = (gn < n)
                ? *reinterpret_cast<const float4*>(&A[(size_t)gn * 64 + k0 + kp])
                : make_float4(0.f, 0.f, 0.f, 0.f);
            As[kp][node] = v.x; As[kp + 1][node] = v.y;
            As[kp + 2][node] = v.z; As[kp + 3][node] = v.w;
        }
        __syncthreads();
        #pragma unroll
        for (int kk = 0; kk < 16; kk++) {
            float a = As[kk][tid];
            #pragma unroll
            for (int c = 0; c < 10; c++) acc[c] += a * Ws[k0 + kk][c];
        }
        __syncthreads();
    }
    int gn = n0 + tid;
    if (gn < n) {
        float dsc = g_dinv[gn];
        #pragma unroll
        for (int c = 0; c < 10; c++) C[(size_t)gn * 10 + c] = acc[c] * dsc;
    }
}

// ---------------- propagation, 64ch fp32 pure-ADD: warp per node ----------------
// Input rows already dinv[src]-scaled; out = relu(dinv[d]*(sum + self) + b).
__global__ void prop64(const float* __restrict__ Tin, float* __restrict__ Hout,
                       const float* __restrict__ bias, int n, int do_relu) {
    int gtid = blockIdx.x * blockDim.x + threadIdx.x;
    int v = gtid >> 5;
    int lane = threadIdx.x & 31;
    if (v >= n) return;

    const float2* __restrict__ T2 = reinterpret_cast<const float2*>(Tin);
    float2 acc = T2[(size_t)v * 32 + lane];   // self term (already scaled)

    int e0 = g_rowptr[v], e1 = g_rowptr[v + 1];
    for (int base = e0; base < e1; base += 32) {
        int ne = min(32, e1 - base);
        int e = 0;
        if (lane < ne) e = g_ecol[base + lane];
        #pragma unroll 8
        for (int j = 0; j < ne; j++) {
            int src = __shfl_sync(0xffffffffu, e, j);
            float2 hh = T2[(size_t)src * 32 + lane];
            acc.x += hh.x;
            acc.y += hh.y;
        }
    }
    float dd = g_dinv[v];
    float2 b = reinterpret_cast<const float2*>(bias)[lane];
    acc.x = acc.x * dd + b.x;
    acc.y = acc.y * dd + b.y;
    if (do_relu) {
        acc.x = fmaxf(acc.x, 0.f);
        acc.y = fmaxf(acc.y, 0.f);
    }
    reinterpret_cast<float2*>(Hout)[(size_t)v * 32 + lane] = acc;
}

// ---------------- propagation 10ch pure-ADD + fused mean-pool ----------------
__global__ void prop10_pool(const float* __restrict__ Tin, const float* __restrict__ bias,
                            const int* __restrict__ batch, int n) {
    int gtid = blockIdx.x * blockDim.x + threadIdx.x;
    int v = gtid >> 5;
    int lane = threadIdx.x & 31;
    if (v >= n) return;

    float acc = 0.f;
    if (lane < NUM_CLASSES) acc = Tin[(size_t)v * 10 + lane];   // self

    int e0 = g_rowptr[v], e1 = g_rowptr[v + 1];
    for (int base = e0; base < e1; base += 32) {
        int ne = min(32, e1 - base);
        int e = 0;
        if (lane < ne) e = g_ecol[base + lane];
        #pragma unroll 8
        for (int j = 0; j < ne; j++) {
            int src = __shfl_sync(0xffffffffu, e, j);
            if (lane < NUM_CLASSES)
                acc += Tin[(size_t)src * 10 + lane];
        }
    }
    int g = batch[v];
    if (lane < NUM_CLASSES)
        atomicAdd(&g_pool[g * 10 + lane], acc * g_dinv[v] + bias[lane]);
    if (lane == NUM_CLASSES)
        atomicAdd(&g_pcnt[g], 1.f);
}

// ---------------- final mean + log_softmax (self-restoring) ----------------
__global__ void final_kernel(float* __restrict__ out) {
    int g = threadIdx.x;
    if (g >= NUM_GRAPHS) return;
    float inv = 1.f / fmaxf(g_pcnt[g], 1.f);
    float v[NUM_CLASSES];
    float m = -1e30f;
    #pragma unroll
    for (int c = 0; c < NUM_CLASSES; c++) {
        v[c] = g_pool[g * 10 + c] * inv;
        m = fmaxf(m, v[c]);
    }
    float ssum = 0.f;
    #pragma unroll
    for (int c = 0; c < NUM_CLASSES; c++) ssum += expf(v[c] - m);
    float lse = m + logf(ssum);
    #pragma unroll
    for (int c = 0; c < NUM_CLASSES; c++) {
        out[g * 10 + c] = v[c] - lse;
        g_pool[g * 10 + c] = 0.f;
    }
    g_pcnt[g] = 0.f;
}

// ---------------- launch ----------------
extern "C" void kernel_launch(void* const* d_in, const int* in_sizes, int n_in,
                              void* d_out, int out_size) {
    const float* x   = (const float*)d_in[0];
    const int*   ei  = (const int*)d_in[1];
    const int*   bat = (const int*)d_in[2];
    const float* W1  = (const float*)d_in[3];
    const float* b1  = (const float*)d_in[4];
    const float* W2  = (const float*)d_in[5];
    const float* b2  = (const float*)d_in[6];
    const float* W3  = (const float*)d_in[7];
    const float* b3  = (const float*)d_in[8];
    float* out = (float*)d_out;

    float* t = nullptr; float* h = nullptr; float* t10 = nullptr;
    cudaGetSymbolAddress((void**)&t, g_t);
    cudaGetSymbolAddress((void**)&h, g_h);
    cudaGetSymbolAddress((void**)&t10, g_t10);

    const size_t GSM1 = (size_t)128 * (IN_CH + 8) * 2 + (size_t)IN_CH * 72 * 2;  // 53248
    const size_t GSM2_raw = (size_t)128 * (HID + 8) * 2 + (size_t)HID * 72 * 2;  // 27648
    const size_t GSM2 = GSM2_raw > 36864 ? GSM2_raw : 36864;

    static cudaStream_t s2 = nullptr;
    static cudaEvent_t evFork = nullptr, evDinv = nullptr, evJoin = nullptr;
    if (s2 == nullptr) {
        cudaStreamCreateWithFlags(&s2, cudaStreamNonBlocking);
        cudaEventCreateWithFlags(&evFork, cudaEventDisableTiming);
        cudaEventCreateWithFlags(&evDinv, cudaEventDisableTiming);
        cudaEventCreateWithFlags(&evJoin, cudaEventDisableTiming);
        cudaFuncSetAttribute(gemm64_hmma<IN_CH>,
                             cudaFuncAttributeMaxDynamicSharedMemorySize, (int)GSM1);
        cudaFuncSetAttribute(gemm64_hmma<HID>,
                             cudaFuncAttributeMaxDynamicSharedMemorySize, (int)GSM2);
    }

    const int TB = 256;
    int nblk  = (N_NODES + TB - 1) / TB;
    int eblk  = (N_EDGES + TB - 1) / TB;
    int wblk  = (N_NODES * 32 + TB - 1) / TB;
    int gblk  = (N_NODES + 127) / 128;

    // ---- fork: preprocessing on s2; GEMM-1 on main waits only for dinv ----
    cudaEventRecord(evFork, 0);
    cudaStreamWaitEvent(s2, evFork, 0);

    count_kernel<<<eblk, TB, 0, s2>>>(ei);            // launch 1
    build_rowptr<<<SCAN_NBLK, SCAN_BS, 0, s2>>>();    // launch 2
    cudaEventRecord(evDinv, s2);
    scatter_kernel<<<eblk, TB, 0, s2>>>(ei);          // launch 3
    cudaEventRecord(evJoin, s2);

    cudaStreamWaitEvent(0, evDinv, 0);
    gemm64_hmma<IN_CH><<<gblk, TB, GSM1>>>(x, W1, t, N_NODES);  // launch 4 — PROFILED

    cudaStreamWaitEvent(0, evJoin, 0);

    prop64<<<wblk, TB>>>(t, h, b1, N_NODES, 1);       // launch 5
    gemm64_hmma<HID><<<gblk, TB, GSM2>>>(h, W2, t, N_NODES);
    prop64<<<wblk, TB>>>(t, h, b2, N_NODES, 1);
    gemm_out10<<<nblk, TB>>>(h, W3, t10, N_NODES);
    prop10_pool<<<wblk, TB>>>(t10, b3, bat, N_NODES);

    final_kernel<<<1, 64>>>(out);
}